// round 4
// baseline (speedup 1.0000x reference)
#include <cuda_runtime.h>

#define BATCH 4
#define SEQ   2048
#define INF   4096
#define OUTF  4096
#define RANK  16
// SCALING = 16/16 = 1.0f (elided)

// ---- phase-1 ----
#define SPLITS 16
#define KSPLIT (INF / SPLITS)     // 256
#define CHUNK  16
#define NCH    (KSPLIT / CHUNK)   // 16
#define ROWS1  512                // 4 rows/thread x 128 lanes
#define T1     256                // 2 rank-groups x 128
#define XP     18                 // x row pitch (floats); 9 ull -> 2-way floor
#define XS_F   (ROWS1 * XP)       // 9216 floats / stage
#define BS_F   (RANK * KSPLIT)    // 4096 floats
#define SMEM1  ((2 * XS_F + BS_F) * 4)   // 90112 B

// ---- phase-2 ----
#define T2     256
#define ROWS2  128
#define OPT    4
#define OTILE  (T2 * OPT)         // 1024
#define BXP    9                  // ulonglong2 pitch

typedef unsigned long long ull;

__device__ float g_bx[SPLITS * BATCH * SEQ * RANK];   // 8 MB scratch

__device__ __forceinline__ void fma2(ull& d, ull a, ull b) {
    asm("fma.rn.f32x2 %0, %1, %2, %0;" : "+l"(d) : "l"(a), "l"(b));
}
__device__ __forceinline__ ull pack2(float lo, float hi) {
    ull d; asm("mov.b64 %0, {%1, %2};" : "=l"(d) : "f"(lo), "f"(hi)); return d;
}
__device__ __forceinline__ void unpack2(float& lo, float& hi, ull d) {
    asm("mov.b64 {%0, %1}, %2;" : "=f"(lo), "=f"(hi) : "l"(d));
}

// ---------------------------------------------------------------------------
// Phase 1: Bx_part[s][b][n][r] = sum_{k in split s} x[b][n][k] * B[aid][r][k]
// ---------------------------------------------------------------------------
#define LOADREGS(CH) do { const int c0_ = k0 + (CH) * CHUNK;                  \
    _Pragma("unroll")                                                         \
    for (int w = 0; w < 8; ++w) {                                             \
        const int idx = w * T1 + tid;                                         \
        const int row = idx >> 2, j4 = idx & 3;                               \
        xr[w] = *(const float4*)(xbase + (size_t)(n0 + row) * INF + c0_ + 4 * j4); \
    } } while (0)

#define STSREGS(XS) do {                                                      \
    _Pragma("unroll")                                                         \
    for (int w = 0; w < 8; ++w) {                                             \
        const int idx = w * T1 + tid;                                         \
        const int row = idx >> 2, j4 = idx & 3;                               \
        float* d_ = (XS) + row * XP + 4 * j4;                                 \
        *(float2*)(d_)     = make_float2(xr[w].x, xr[w].y);                   \
        *(float2*)(d_ + 2) = make_float2(xr[w].z, xr[w].w);                   \
    } } while (0)

#define COMPUTE(XS, CH) do {                                                  \
    const float* xp0 = (XS) + lt * XP;                                        \
    _Pragma("unroll")                                                         \
    for (int j = 0; j < 4; ++j) {                                             \
        const int cc = (CH) * CHUNK + 4 * j;                                  \
        ull xv[4][2];                                                         \
        _Pragma("unroll")                                                     \
        for (int q = 0; q < 4; ++q) {                                         \
            const float* xq = xp0 + q * 128 * XP + 4 * j;                     \
            xv[q][0] = *(const ull*)(xq);                                     \
            xv[q][1] = *(const ull*)(xq + 2);                                 \
        }                                                                     \
        _Pragma("unroll")                                                     \
        for (int r = 0; r < 8; ++r) {                                         \
            const ulonglong2 bv = *(const ulonglong2*)(bsm + r * KSPLIT + cc); \
            _Pragma("unroll")                                                 \
            for (int q = 0; q < 4; ++q) {                                     \
                fma2(acc[r][q], xv[q][0], bv.x);                              \
                fma2(acc[r][q], xv[q][1], bv.y);                              \
            }                                                                 \
        }                                                                     \
    } } while (0)

__global__ __launch_bounds__(T1, 2) void lora_phase1(
    const float* __restrict__ x,
    const float* __restrict__ Bw,
    const int*   __restrict__ ids)
{
    extern __shared__ float sm[];
    float* const xs0 = sm;
    float* const xs1 = sm + XS_F;
    float* const bs  = sm + 2 * XS_F;

    const int tid = threadIdx.x;
    const int n0  = blockIdx.x * ROWS1;
    const int b   = blockIdx.y;
    const int s   = blockIdx.z;
    const int aid = ids[b];
    const int k0  = s * KSPLIT;
    const int g   = tid >> 7;            // rank group: ranks g*8..g*8+7
    const int lt  = tid & 127;           // rows lt + 128q, q=0..3

    const float* xbase = x  + (size_t)b * SEQ * INF;
    const float* Bbase = Bw + (size_t)aid * RANK * INF;
    const float* bsm   = bs + g * 8 * KSPLIT;

    // load B slice once: 16 ranks x 256 k (coalesced float4)
#pragma unroll
    for (int t = 0; t < 4; ++t) {
        const int i = t * T1 + tid;      // 0..1023 float4s
        const int r = i >> 6, c = i & 63;
        *(float4*)(bs + r * KSPLIT + 4 * c) =
            *(const float4*)(Bbase + (size_t)r * INF + k0 + 4 * c);
    }

    ull acc[8][4];
#pragma unroll
    for (int r = 0; r < 8; ++r)
#pragma unroll
        for (int q = 0; q < 4; ++q) acc[r][q] = 0ull;

    float4 xr[8];
    LOADREGS(0);
    STSREGS(xs0);
    LOADREGS(1);
    __syncthreads();

#pragma unroll 1
    for (int ch = 0; ch < NCH; ++ch) {
        if (ch & 1) {
            COMPUTE(xs1, ch);
            if (ch + 1 < NCH) {
                STSREGS(xs0);
                if (ch + 2 < NCH) LOADREGS(ch + 2);
                __syncthreads();
            }
        } else {
            COMPUTE(xs0, ch);
            if (ch + 1 < NCH) {
                STSREGS(xs1);
                if (ch + 2 < NCH) LOADREGS(ch + 2);
                __syncthreads();
            }
        }
    }

    // horizontal pair-add; store 8 ranks per row for 4 rows
    const size_t slot = ((size_t)s * BATCH + b) * SEQ;
#pragma unroll
    for (int q = 0; q < 4; ++q) {
        float* d = g_bx + (slot + n0 + lt + 128 * q) * RANK + g * 8;
        float l, h; float4 v0, v1;
        unpack2(l, h, acc[0][q]); v0.x = l + h;
        unpack2(l, h, acc[1][q]); v0.y = l + h;
        unpack2(l, h, acc[2][q]); v0.z = l + h;
        unpack2(l, h, acc[3][q]); v0.w = l + h;
        unpack2(l, h, acc[4][q]); v1.x = l + h;
        unpack2(l, h, acc[5][q]); v1.y = l + h;
        unpack2(l, h, acc[6][q]); v1.z = l + h;
        unpack2(l, h, acc[7][q]); v1.w = l + h;
        ((float4*)d)[0] = v0;
        ((float4*)d)[1] = v1;
    }
}

// ---------------------------------------------------------------------------
// Reduce 16 split partials into slot 0.
// ---------------------------------------------------------------------------
__global__ void lora_reduce()
{
    const int total = BATCH * SEQ * RANK / 4;     // 32768 float4
    const int idx = blockIdx.x * blockDim.x + threadIdx.x;
    if (idx >= total) return;
    float4* p = (float4*)g_bx;
    float4 a = p[idx];
#pragma unroll
    for (int s = 1; s < SPLITS; ++s) {
        const float4 v = p[(size_t)s * total + idx];
        a.x += v.x; a.y += v.y; a.z += v.z; a.w += v.w;
    }
    p[idx] = a;
}

// ---------------------------------------------------------------------------
// Phase 2: out[b][n][o] = sum_r Bx[b][n][r] * A[aid][o][r]
// Thread owns 4 consecutive o; A pairs (32 ull) in regs; Bx dup'd in smem.
// 4 accumulator chains (o-pairs x rank-halves).
// ---------------------------------------------------------------------------
__global__ __launch_bounds__(T2, 2) void lora_phase2(
    const float* __restrict__ Aw,
    const int*   __restrict__ ids,
    float*       __restrict__ out)
{
    __shared__ ulonglong2 bxd[ROWS2 * BXP];       // 18.4 KB

    const int tid = threadIdx.x;
    const int o   = blockIdx.x * OTILE + tid * OPT;
    const int n0  = blockIdx.y * ROWS2;
    const int b   = blockIdx.z;
    const int aid = ids[b];

    // ap01[r] = (A[o][r], A[o+1][r]); ap23[r] = (A[o+2][r], A[o+3][r])
    ull ap01[16], ap23[16];
    {
        const float* Ab = Aw + ((size_t)aid * OUTF + o) * RANK;
        float a0[16], a1[16], a2[16], a3[16];
#pragma unroll
        for (int j = 0; j < 4; ++j) {
            float4 v;
            v = *(const float4*)(Ab + 0 * RANK + 4 * j);
            a0[4*j]=v.x; a0[4*j+1]=v.y; a0[4*j+2]=v.z; a0[4*j+3]=v.w;
            v = *(const float4*)(Ab + 1 * RANK + 4 * j);
            a1[4*j]=v.x; a1[4*j+1]=v.y; a1[4*j+2]=v.z; a1[4*j+3]=v.w;
            v = *(const float4*)(Ab + 2 * RANK + 4 * j);
            a2[4*j]=v.x; a2[4*j+1]=v.y; a2[4*j+2]=v.z; a2[4*j+3]=v.w;
            v = *(const float4*)(Ab + 3 * RANK + 4 * j);
            a3[4*j]=v.x; a3[4*j+1]=v.y; a3[4*j+2]=v.z; a3[4*j+3]=v.w;
        }
#pragma unroll
        for (int r = 0; r < 16; ++r) {
            ap01[r] = pack2(a0[r], a1[r]);
            ap23[r] = pack2(a2[r], a3[r]);
        }
    }

    // stage Bx rows duplicated: bxd[n][p] = ((v2p,v2p),(v2p+1,v2p+1))
    if (tid < ROWS2) {
        const float* src = g_bx + ((size_t)b * SEQ + n0 + tid) * RANK;
        float v[16];
#pragma unroll
        for (int j = 0; j < 4; ++j) {
            const float4 t = *(const float4*)(src + 4 * j);
            v[4*j]=t.x; v[4*j+1]=t.y; v[4*j+2]=t.z; v[4*j+3]=t.w;
        }
#pragma unroll
        for (int p = 0; p < 8; ++p) {
            ulonglong2 e;
            e.x = pack2(v[2*p],   v[2*p]);
            e.y = pack2(v[2*p+1], v[2*p+1]);
            bxd[tid * BXP + p] = e;
        }
    }
    __syncthreads();

    float4* outp = (float4*)(out + ((size_t)b * SEQ + n0) * OUTF + o);

#pragma unroll 2
    for (int n = 0; n < ROWS2; ++n) {
        const ulonglong2* row = bxd + n * BXP;
        ull s0a = 0ull, s0b = 0ull, s1a = 0ull, s1b = 0ull;  // 4 chains
#pragma unroll
        for (int p = 0; p < 4; ++p) {                        // ranks 0-7
            const ulonglong2 bb = row[p];
            fma2(s0a, ap01[2*p],   bb.x); fma2(s0a, ap01[2*p+1], bb.y);
            fma2(s1a, ap23[2*p],   bb.x); fma2(s1a, ap23[2*p+1], bb.y);
        }
#pragma unroll
        for (int p = 4; p < 8; ++p) {                        // ranks 8-15
            const ulonglong2 bb = row[p];
            fma2(s0b, ap01[2*p],   bb.x); fma2(s0b, ap01[2*p+1], bb.y);
            fma2(s1b, ap23[2*p],   bb.x); fma2(s1b, ap23[2*p+1], bb.y);
        }
        float4 res;
        float l0, h0, l1, h1;
        unpack2(l0, h0, s0a); unpack2(l1, h1, s0b);
        res.x = l0 + l1; res.y = h0 + h1;
        unpack2(l0, h0, s1a); unpack2(l1, h1, s1b);
        res.z = l0 + l1; res.w = h0 + h1;
        outp[(size_t)n * (OUTF / 4)] = res;
    }
}

// ---------------------------------------------------------------------------
extern "C" void kernel_launch(void* const* d_in, const int* in_sizes, int n_in,
                              void* d_out, int out_size)
{
    const float* x   = (const float*)d_in[0];
    const float* Aw  = (const float*)d_in[1];
    const float* Bw  = (const float*)d_in[2];
    const int*   ids = (const int*)  d_in[3];
    float*       out = (float*)d_out;

    cudaFuncSetAttribute(lora_phase1,
                         cudaFuncAttributeMaxDynamicSharedMemorySize, SMEM1);

    dim3 g1(SEQ / ROWS1, BATCH, SPLITS);          // (4,4,16) = 256 CTAs
    lora_phase1<<<g1, T1, SMEM1>>>(x, Bw, ids);

    lora_reduce<<<(BATCH * SEQ * RANK / 4) / 256, 256>>>();

    dim3 g2(OUTF / OTILE, SEQ / ROWS2, BATCH);    // (4,16,4) = 256 CTAs
    lora_phase2<<<g2, T2>>>(Aw, ids, out);
}

// round 5
// speedup vs baseline: 1.1012x; 1.1012x over previous
#include <cuda_runtime.h>
#include <cstdint>

#define BATCH 4
#define SEQ   2048
#define INF   4096
#define OUTF  4096
#define RANK  16
// SCALING = 16/16 = 1.0f (elided)

// ---- phase-1 ----
#define SPLITS 8
#define KSPLIT (INF / SPLITS)          // 512
#define CHUNK  32
#define NCH    (KSPLIT / CHUNK)        // 16
#define ROWS1  512                     // 4 rows/thread x 128 lanes
#define T1     256                     // 2 rank-groups x 128 lanes
#define XP     33                      // x pitch in floats: conflict-free LDS.32
#define XSTG   (ROWS1 * XP)            // 16896 floats per stage
#define BSTG   (RANK * CHUNK)          // 512 floats per stage
#define STG_F  (XSTG + BSTG)           // 17408
#define NSTAGE 3
#define SMEM1  (NSTAGE * STG_F * 4)    // 208896 B

// ---- phase-2 ----
#define T2     256
#define ROWS2  128
#define OPT    4
#define OTILE  (T2 * OPT)              // 1024
#define BXP    9

typedef unsigned long long ull;

__device__ float g_bx[SPLITS * BATCH * SEQ * RANK];   // 4 MB split partials

// ---- packed f32x2 + cp.async helpers -------------------------------------
__device__ __forceinline__ void fma2(ull& d, ull a, ull b) {
    asm("fma.rn.f32x2 %0, %1, %2, %0;" : "+l"(d) : "l"(a), "l"(b));
}
__device__ __forceinline__ ull pack2(float lo, float hi) {
    ull d; asm("mov.b64 %0, {%1, %2};" : "=l"(d) : "f"(lo), "f"(hi)); return d;
}
__device__ __forceinline__ void unpack2(float& lo, float& hi, ull d) {
    asm("mov.b64 {%0, %1}, %2;" : "=f"(lo), "=f"(hi) : "l"(d));
}
__device__ __forceinline__ void cp4(uint32_t dst, const float* src) {
    asm volatile("cp.async.ca.shared.global [%0], [%1], 4;" :: "r"(dst), "l"(src));
}
__device__ __forceinline__ void cp_commit() {
    asm volatile("cp.async.commit_group;");
}
__device__ __forceinline__ void cp_wait1() {
    asm volatile("cp.async.wait_group 1;");
}

// ---------------------------------------------------------------------------
// Phase 1: Bx_part[s][b][n][r] = sum_{k in split s} x[b][n][k] * B[aid][r][k]
// 256 threads = 2 rank-groups(8) x 128 lanes, 4 rows/lane (lt + 128q).
// cp.async 3-stage ring, one barrier per chunk.
// ---------------------------------------------------------------------------
__global__ __launch_bounds__(T1, 1) void lora_phase1(
    const float* __restrict__ x,
    const float* __restrict__ Bw,
    const int*   __restrict__ ids)
{
    extern __shared__ float sm[];

    const int tid = threadIdx.x;
    const int n0  = blockIdx.x * ROWS1;
    const int b   = blockIdx.y;
    const int s   = blockIdx.z;
    const int aid = ids[b];
    const int k0  = s * KSPLIT;
    const int g   = tid >> 7;          // rank group: ranks g*8 .. g*8+7
    const int lt  = tid & 127;         // rows lt + 128q

    const float* xbase = x  + (size_t)b * SEQ * INF;
    const float* Bbase = Bw + (size_t)aid * RANK * INF;
    const uint32_t smb = (uint32_t)__cvta_generic_to_shared(sm);

    // issue cp.async for chunk ch into stage st
    auto issue = [&](int ch, int st) {
        const int cc = k0 + ch * CHUNK;
        const uint32_t sb = smb + (uint32_t)(st * STG_F) * 4u;
        // x: 512 rows x 32 floats, 64 cps/thread, 32 lanes = 128B lines
#pragma unroll
        for (int i = 0; i < 64; ++i) {
            const int f   = i * T1 + tid;
            const int row = f >> 5, col = f & 31;
            cp4(sb + (uint32_t)(row * XP + col) * 4u,
                xbase + (size_t)(n0 + row) * INF + cc + col);
        }
        // B: 16 ranks x 32 floats, 2 cps/thread
#pragma unroll
        for (int i = 0; i < 2; ++i) {
            const int f = i * T1 + tid;
            const int r = f >> 5, col = f & 31;
            cp4(sb + (uint32_t)(XSTG + r * CHUNK + col) * 4u,
                Bbase + (size_t)r * INF + cc + col);
        }
    };

    ull acc[8][4];
#pragma unroll
    for (int r = 0; r < 8; ++r)
#pragma unroll
        for (int q = 0; q < 4; ++q) acc[r][q] = 0ull;

    issue(0, 0); cp_commit();
    issue(1, 1); cp_commit();

#pragma unroll 1
    for (int ch = 0; ch < NCH; ++ch) {
        cp_wait1();
        __syncthreads();                       // all of chunk ch visible; stage
                                               // (ch+2)%3 fully consumed (iter ch-1)
        if (ch + 2 < NCH) issue(ch + 2, (ch + 2) % NSTAGE);
        cp_commit();                           // empty group ok near tail

        const float* xs  = sm + (ch % NSTAGE) * STG_F;
        const float* bsm = xs + XSTG + g * 8 * CHUNK;
#pragma unroll
        for (int j = 0; j < CHUNK / 4; ++j) {  // 8 iters of 4 k's
            ull xv[4][2];
#pragma unroll
            for (int q = 0; q < 4; ++q) {
                const float* xr = xs + (lt + 128 * q) * XP + 4 * j;
                xv[q][0] = pack2(xr[0], xr[1]);   // LDS.32 conflict-free (pitch 33)
                xv[q][1] = pack2(xr[2], xr[3]);
            }
#pragma unroll
            for (int r = 0; r < 8; ++r) {
                const ulonglong2 bv =
                    *(const ulonglong2*)(bsm + r * CHUNK + 4 * j);  // broadcast
#pragma unroll
                for (int q = 0; q < 4; ++q) {
                    fma2(acc[r][q], xv[q][0], bv.x);
                    fma2(acc[r][q], xv[q][1], bv.y);
                }
            }
        }
    }

    // horizontal pair-add; store 8 ranks x 4 rows
    const size_t slot = ((size_t)s * BATCH + b) * SEQ;
#pragma unroll
    for (int q = 0; q < 4; ++q) {
        float* d = g_bx + (slot + n0 + lt + 128 * q) * RANK + g * 8;
        float l, h; float4 v0, v1;
        unpack2(l, h, acc[0][q]); v0.x = l + h;
        unpack2(l, h, acc[1][q]); v0.y = l + h;
        unpack2(l, h, acc[2][q]); v0.z = l + h;
        unpack2(l, h, acc[3][q]); v0.w = l + h;
        unpack2(l, h, acc[4][q]); v1.x = l + h;
        unpack2(l, h, acc[5][q]); v1.y = l + h;
        unpack2(l, h, acc[6][q]); v1.z = l + h;
        unpack2(l, h, acc[7][q]); v1.w = l + h;
        ((float4*)d)[0] = v0;
        ((float4*)d)[1] = v1;
    }
}

// ---------------------------------------------------------------------------
// Phase 2 (with fused split-reduce): out[b][n][o] = sum_r Bx[b][n][r]*A[aid][o][r]
// Staging: thread pair per row sums the 8 partials (L2-resident) and writes
// rank-duplicated pairs to smem. Main loop: 2 rows/iter, 8 fma2 chains.
// ---------------------------------------------------------------------------
__global__ __launch_bounds__(T2, 2) void lora_phase2(
    const float* __restrict__ Aw,
    const int*   __restrict__ ids,
    float*       __restrict__ out)
{
    __shared__ ulonglong2 bxd[ROWS2 * BXP];      // 18.4 KB

    const int tid = threadIdx.x;
    const int o   = blockIdx.x * OTILE + tid * OPT;
    const int n0  = blockIdx.y * ROWS2;
    const int b   = blockIdx.z;
    const int aid = ids[b];

    // A pairs: ap01[r] = (A[o][r], A[o+1][r]); ap23[r] = (A[o+2][r], A[o+3][r])
    ull ap01[16], ap23[16];
    {
        const float* Ab = Aw + ((size_t)aid * OUTF + o) * RANK;
        float a0[16], a1[16], a2[16], a3[16];
#pragma unroll
        for (int j = 0; j < 4; ++j) {
            float4 v;
            v = *(const float4*)(Ab + 0 * RANK + 4 * j);
            a0[4*j]=v.x; a0[4*j+1]=v.y; a0[4*j+2]=v.z; a0[4*j+3]=v.w;
            v = *(const float4*)(Ab + 1 * RANK + 4 * j);
            a1[4*j]=v.x; a1[4*j+1]=v.y; a1[4*j+2]=v.z; a1[4*j+3]=v.w;
            v = *(const float4*)(Ab + 2 * RANK + 4 * j);
            a2[4*j]=v.x; a2[4*j+1]=v.y; a2[4*j+2]=v.z; a2[4*j+3]=v.w;
            v = *(const float4*)(Ab + 3 * RANK + 4 * j);
            a3[4*j]=v.x; a3[4*j+1]=v.y; a3[4*j+2]=v.z; a3[4*j+3]=v.w;
        }
#pragma unroll
        for (int r = 0; r < 16; ++r) {
            ap01[r] = pack2(a0[r], a1[r]);
            ap23[r] = pack2(a2[r], a3[r]);
        }
    }

    // fused reduce + duplicate staging: 2 threads per row, 8 ranks each
    {
        const int row  = tid >> 1;
        const int half = tid & 1;
        const float* base = g_bx + ((size_t)b * SEQ + n0 + row) * RANK + half * 8;
        float4 u = make_float4(0.f, 0.f, 0.f, 0.f);
        float4 v = make_float4(0.f, 0.f, 0.f, 0.f);
#pragma unroll
        for (int s = 0; s < SPLITS; ++s) {
            const float4* p =
                (const float4*)(base + (size_t)s * BATCH * SEQ * RANK);
            const float4 pa = p[0], pb = p[1];
            u.x += pa.x; u.y += pa.y; u.z += pa.z; u.w += pa.w;
            v.x += pb.x; v.y += pb.y; v.z += pb.z; v.w += pb.w;
        }
        const float w[8] = {u.x, u.y, u.z, u.w, v.x, v.y, v.z, v.w};
#pragma unroll
        for (int i = 0; i < 4; ++i) {
            ulonglong2 e;
            e.x = pack2(w[2*i],   w[2*i]);
            e.y = pack2(w[2*i+1], w[2*i+1]);
            bxd[row * BXP + half * 4 + i] = e;
        }
    }
    __syncthreads();

    float4* outp = (float4*)(out + ((size_t)b * SEQ + n0) * OUTF + o);

#pragma unroll 1
    for (int n = 0; n < ROWS2; n += 2) {
        const ulonglong2* r0 = bxd + n * BXP;
        const ulonglong2* r1 = r0 + BXP;
        ull A0=0, A1=0, A2=0, A3=0, B0=0, B1=0, B2=0, B3=0;
#pragma unroll
        for (int p = 0; p < 4; ++p) {            // ranks 0-7
            const ulonglong2 ba = r0[p], bb = r1[p];
            fma2(A0, ap01[2*p], ba.x); fma2(A0, ap01[2*p+1], ba.y);
            fma2(A1, ap23[2*p], ba.x); fma2(A1, ap23[2*p+1], ba.y);
            fma2(B0, ap01[2*p], bb.x); fma2(B0, ap01[2*p+1], bb.y);
            fma2(B1, ap23[2*p], bb.x); fma2(B1, ap23[2*p+1], bb.y);
        }
#pragma unroll
        for (int p = 4; p < 8; ++p) {            // ranks 8-15
            const ulonglong2 ba = r0[p], bb = r1[p];
            fma2(A2, ap01[2*p], ba.x); fma2(A2, ap01[2*p+1], ba.y);
            fma2(A3, ap23[2*p], ba.x); fma2(A3, ap23[2*p+1], ba.y);
            fma2(B2, ap01[2*p], bb.x); fma2(B2, ap01[2*p+1], bb.y);
            fma2(B3, ap23[2*p], bb.x); fma2(B3, ap23[2*p+1], bb.y);
        }
        float4 res0, res1;
        float l0, h0, l1, h1;
        unpack2(l0, h0, A0); unpack2(l1, h1, A2); res0.x = l0+l1; res0.y = h0+h1;
        unpack2(l0, h0, A1); unpack2(l1, h1, A3); res0.z = l0+l1; res0.w = h0+h1;
        unpack2(l0, h0, B0); unpack2(l1, h1, B2); res1.x = l0+l1; res1.y = h0+h1;
        unpack2(l0, h0, B1); unpack2(l1, h1, B3); res1.z = l0+l1; res1.w = h0+h1;
        outp[(size_t)n       * (OUTF / 4)] = res0;
        outp[(size_t)(n + 1) * (OUTF / 4)] = res1;
    }
}

// ---------------------------------------------------------------------------
extern "C" void kernel_launch(void* const* d_in, const int* in_sizes, int n_in,
                              void* d_out, int out_size)
{
    const float* x   = (const float*)d_in[0];   // [4,2048,4096]
    const float* Aw  = (const float*)d_in[1];   // [8,4096,16]
    const float* Bw  = (const float*)d_in[2];   // [8,16,4096]
    const int*   ids = (const int*)  d_in[3];   // [4]
    float*       out = (float*)d_out;           // [4,2048,4096]

    cudaFuncSetAttribute(lora_phase1,
                         cudaFuncAttributeMaxDynamicSharedMemorySize, SMEM1);

    dim3 g1(SEQ / ROWS1, BATCH, SPLITS);        // (4,4,8) = 128 CTAs, 1 wave
    lora_phase1<<<g1, T1, SMEM1>>>(x, Bw, ids);

    dim3 g2(OUTF / OTILE, SEQ / ROWS2, BATCH);  // (4,16,4) = 256 CTAs
    lora_phase2<<<g2, T2>>>(Aw, ids, out);
}

// round 6
// speedup vs baseline: 1.3343x; 1.2116x over previous
#include <cuda_runtime.h>
#include <cstdint>

#define BATCH 4
#define SEQ   2048
#define INF   4096
#define OUTF  4096
#define RANK  16
// SCALING = 16/16 = 1.0f (elided)

// ---- phase-1 ----
#define SPLITS 8
#define KSPLIT (INF / SPLITS)      // 512
#define CHUNK  32
#define NCH    (KSPLIT / CHUNK)    // 16
#define LANES  64                  // lanes per rank-group
#define LROWS  8                   // rows per thread
#define ROWS1  (LANES * LROWS)     // 512
#define T1     256                 // 4 rank-groups x 64 lanes
#define XP     36                  // floats; 144B rows: 16B-aligned + conflict-free LDS.128
#define XSTG   (ROWS1 * XP)        // 18432 floats
#define BSTG   (RANK * CHUNK)      // 512 floats
#define STG_F  (XSTG + BSTG)       // 18944 floats
#define SMEM1  (2 * STG_F * 4)     // 151552 B

// ---- phase-2 ----
#define T2     256
#define OPT    8
#define OTILE  (T2 * OPT)          // 2048
#define ROWS2  128

typedef unsigned long long ull;

__device__ float g_bx[SPLITS * BATCH * SEQ * RANK];   // 4 MB split partials

// ---- helpers --------------------------------------------------------------
__device__ __forceinline__ void fma2(ull& d, ull a, ull b) {
    asm("fma.rn.f32x2 %0, %1, %2, %0;" : "+l"(d) : "l"(a), "l"(b));
}
__device__ __forceinline__ ull add2(ull a, ull b) {
    ull d; asm("add.rn.f32x2 %0, %1, %2;" : "=l"(d) : "l"(a), "l"(b)); return d;
}
__device__ __forceinline__ ull pack2(float lo, float hi) {
    ull d; asm("mov.b64 %0, {%1, %2};" : "=l"(d) : "f"(lo), "f"(hi)); return d;
}
__device__ __forceinline__ void unpack2(float& lo, float& hi, ull d) {
    asm("mov.b64 {%0, %1}, %2;" : "=f"(lo), "=f"(hi) : "l"(d));
}
__device__ __forceinline__ void cp16(uint32_t dst, const float* src) {
    asm volatile("cp.async.cg.shared.global [%0], [%1], 16;" :: "r"(dst), "l"(src));
}
__device__ __forceinline__ void cp_commit() {
    asm volatile("cp.async.commit_group;");
}
__device__ __forceinline__ void cp_wait0() {
    asm volatile("cp.async.wait_group 0;");
}

// ---------------------------------------------------------------------------
// Phase 1: Bx_part[s][b][n][r] = sum_{k in split s} x[b][n][k] * B[aid][r][k]
// T1=256 = 4 rank-groups (4 ranks each) x 64 lanes; 8 rows/thread.
// Per j: 8 LDS.128 (x, conflict-free) + 4 LDS.128 (B, broadcast) + 64 fma2.
// 2-stage cp.async.cg(16B) pipeline, one barrier per chunk.
// ---------------------------------------------------------------------------
__global__ __launch_bounds__(T1, 1) void lora_phase1(
    const float* __restrict__ x,
    const float* __restrict__ Bw,
    const int*   __restrict__ ids)
{
    extern __shared__ float sm[];

    const int tid = threadIdx.x;
    const int n0  = blockIdx.x * ROWS1;
    const int b   = blockIdx.y;
    const int s   = blockIdx.z;
    const int aid = ids[b];
    const int k0  = s * KSPLIT;
    const int g   = tid >> 6;            // rank group: ranks g*4 .. g*4+3
    const int lt  = tid & 63;            // rows lt + 64q, q=0..7

    const float* xbase = x  + (size_t)b * SEQ * INF;
    const float* Bbase = Bw + (size_t)aid * RANK * INF;
    const uint32_t smb = (uint32_t)__cvta_generic_to_shared(sm);

    auto issue = [&](int ch, int st) {
        const int cc = k0 + ch * CHUNK;
        const uint32_t sb = smb + (uint32_t)(st * STG_F) * 4u;
        // x tile: 512 rows x 8 float4 -> 16 cp16/thread, 8 lanes per 128B row
#pragma unroll
        for (int i = 0; i < 16; ++i) {
            const int f   = i * T1 + tid;
            const int row = f >> 3, j4 = f & 7;
            cp16(sb + (uint32_t)(row * XP + 4 * j4) * 4u,
                 xbase + (size_t)(n0 + row) * INF + cc + 4 * j4);
        }
        // B tile: 16 ranks x 8 float4 -> threads 0..127
        if (tid < 128) {
            const int r = tid >> 3, j4 = tid & 7;
            cp16(sb + (uint32_t)(XSTG + r * CHUNK + 4 * j4) * 4u,
                 Bbase + (size_t)r * INF + cc + 4 * j4);
        }
    };

    ull acc[4][LROWS];
#pragma unroll
    for (int r = 0; r < 4; ++r)
#pragma unroll
        for (int q = 0; q < LROWS; ++q) acc[r][q] = 0ull;

    issue(0, 0); cp_commit();

#pragma unroll 1
    for (int ch = 0; ch < NCH; ++ch) {
        cp_wait0();
        __syncthreads();                 // chunk ch visible to all; stage
                                         // (ch+1)&1 consumed in iter ch-1
        if (ch + 1 < NCH) { issue(ch + 1, (ch + 1) & 1); cp_commit(); }

        const float* xs  = sm + (ch & 1) * STG_F;
        const float* bsm = xs + XSTG + g * 4 * CHUNK;
#pragma unroll
        for (int j = 0; j < CHUNK / 4; ++j) {    // 8 iters of 4 k's
            float4 xv[LROWS];
#pragma unroll
            for (int q = 0; q < LROWS; ++q)
                xv[q] = *(const float4*)(xs + (lt + 64 * q) * XP + 4 * j);
#pragma unroll
            for (int r = 0; r < 4; ++r) {
                const ulonglong2 bv =
                    *(const ulonglong2*)(bsm + r * CHUNK + 4 * j);  // broadcast
#pragma unroll
                for (int q = 0; q < LROWS; ++q) {
                    fma2(acc[r][q], pack2(xv[q].x, xv[q].y), bv.x);
                    fma2(acc[r][q], pack2(xv[q].z, xv[q].w), bv.y);
                }
            }
        }
    }

    // horizontal pair-add; each thread stores 4 ranks x 8 rows
    const size_t slot = ((size_t)s * BATCH + b) * SEQ;
#pragma unroll
    for (int q = 0; q < LROWS; ++q) {
        float* d = g_bx + (slot + n0 + lt + 64 * q) * RANK + g * 4;
        float l, h; float4 v;
        unpack2(l, h, acc[0][q]); v.x = l + h;
        unpack2(l, h, acc[1][q]); v.y = l + h;
        unpack2(l, h, acc[2][q]); v.z = l + h;
        unpack2(l, h, acc[3][q]); v.w = l + h;
        *(float4*)d = v;
    }
}

// ---------------------------------------------------------------------------
// Phase 2 (fused split-reduce): out[b][n][o] = sum_r Bx[b][n][r]*A[aid][o][r]
// Thread owns 8 consecutive o (4 o-pairs); A pairs (64 ull) in registers.
// Bx duplicated pairs stored rank-major bxu[r][row] (1KB stride -> LDS.64,
// un-fusible). Per row-warp: 16 LDS.64 (32 cyc) vs 64 fma2 -> ratio 0.5.
// ---------------------------------------------------------------------------
__global__ __launch_bounds__(T2, 1) void lora_phase2(
    const float* __restrict__ Aw,
    const int*   __restrict__ ids,
    float*       __restrict__ out)
{
    __shared__ ull bxu[RANK][ROWS2];     // 16 KB

    const int tid = threadIdx.x;
    const int o   = blockIdx.x * OTILE + tid * OPT;
    const int n0  = blockIdx.y * ROWS2;
    const int b   = blockIdx.z;
    const int aid = ids[b];

    // A pairs: apP[r] = (A[o+2P][r], A[o+2P+1][r]), P=0..3
    ull ap0[16], ap1[16], ap2[16], ap3[16];
    {
        const float* Ab = Aw + ((size_t)aid * OUTF + o) * RANK;
        float av[8][16];
#pragma unroll
        for (int q = 0; q < 8; ++q)
#pragma unroll
            for (int j = 0; j < 4; ++j) {
                const float4 v = *(const float4*)(Ab + q * RANK + 4 * j);
                av[q][4*j] = v.x; av[q][4*j+1] = v.y;
                av[q][4*j+2] = v.z; av[q][4*j+3] = v.w;
            }
#pragma unroll
        for (int r = 0; r < 16; ++r) {
            ap0[r] = pack2(av[0][r], av[1][r]);
            ap1[r] = pack2(av[2][r], av[3][r]);
            ap2[r] = pack2(av[4][r], av[5][r]);
            ap3[r] = pack2(av[6][r], av[7][r]);
        }
    }

    // fused reduce + duplicated rank-major staging: 2 threads per row
    {
        const int row  = tid >> 1;
        const int half = tid & 1;        // ranks half*8 .. half*8+7
        const float* base = g_bx + ((size_t)b * SEQ + n0 + row) * RANK + half * 8;
        float4 u = make_float4(0.f, 0.f, 0.f, 0.f);
        float4 v = make_float4(0.f, 0.f, 0.f, 0.f);
#pragma unroll
        for (int s = 0; s < SPLITS; ++s) {
            const float4* p = (const float4*)(base + (size_t)s * BATCH * SEQ * RANK);
            const float4 pa = p[0], pb = p[1];
            u.x += pa.x; u.y += pa.y; u.z += pa.z; u.w += pa.w;
            v.x += pb.x; v.y += pb.y; v.z += pb.z; v.w += pb.w;
        }
        const float w[8] = {u.x, u.y, u.z, u.w, v.x, v.y, v.z, v.w};
#pragma unroll
        for (int i = 0; i < 8; ++i)
            bxu[half * 8 + i][row] = pack2(w[i], w[i]);
    }
    __syncthreads();

    float4* outp = (float4*)(out + ((size_t)b * SEQ + n0) * OUTF + o);

#pragma unroll 2
    for (int n = 0; n < ROWS2; ++n) {
        ull c0a=0, c1a=0, c2a=0, c3a=0;     // ranks 0-7
        ull c0b=0, c1b=0, c2b=0, c3b=0;     // ranks 8-15
#pragma unroll
        for (int r = 0; r < 8; ++r) {
            const ull bv = bxu[r][n];        // LDS.64 broadcast
            fma2(c0a, ap0[r], bv); fma2(c1a, ap1[r], bv);
            fma2(c2a, ap2[r], bv); fma2(c3a, ap3[r], bv);
        }
#pragma unroll
        for (int r = 8; r < 16; ++r) {
            const ull bv = bxu[r][n];
            fma2(c0b, ap0[r], bv); fma2(c1b, ap1[r], bv);
            fma2(c2b, ap2[r], bv); fma2(c3b, ap3[r], bv);
        }
        const ull p0 = add2(c0a, c0b), p1 = add2(c1a, c1b);
        const ull p2 = add2(c2a, c2b), p3 = add2(c3a, c3b);
        float4 r0, r1;
        unpack2(r0.x, r0.y, p0); unpack2(r0.z, r0.w, p1);
        unpack2(r1.x, r1.y, p2); unpack2(r1.z, r1.w, p3);
        outp[(size_t)n * (OUTF / 4)]     = r0;
        outp[(size_t)n * (OUTF / 4) + 1] = r1;
    }
}

// ---------------------------------------------------------------------------
extern "C" void kernel_launch(void* const* d_in, const int* in_sizes, int n_in,
                              void* d_out, int out_size)
{
    const float* x   = (const float*)d_in[0];   // [4,2048,4096]
    const float* Aw  = (const float*)d_in[1];   // [8,4096,16]
    const float* Bw  = (const float*)d_in[2];   // [8,16,4096]
    const int*   ids = (const int*)  d_in[3];   // [4]
    float*       out = (float*)d_out;           // [4,2048,4096]

    cudaFuncSetAttribute(lora_phase1,
                         cudaFuncAttributeMaxDynamicSharedMemorySize, SMEM1);

    dim3 g1(SEQ / ROWS1, BATCH, SPLITS);        // (4,4,8) = 128 CTAs
    lora_phase1<<<g1, T1, SMEM1>>>(x, Bw, ids);

    dim3 g2(OUTF / OTILE, SEQ / ROWS2, BATCH);  // (2,16,4) = 128 CTAs
    lora_phase2<<<g2, T2>>>(Aw, ids, out);
}